// round 8
// baseline (speedup 1.0000x reference)
#include <cuda_runtime.h>
#include <math.h>

constexpr int NB = 128, NA = 2, NH = 128, NW = 128;
constexpr int PLANE = NH * NW;
constexpr float THRESH = 0.6f;
constexpr float OBJ_SCALE = 5.0f;
constexpr float LN_MARGIN = 0.55961579f;   // ln(1.75) > ln(5/3)+fastlog-err margin
constexpr int NBLOCKS = 2048;              // 524288 threads * 8 cells

// Accumulators (zero at module load; reset by last block each run)
__device__ double g_conf2 = 0.0;
__device__ unsigned long long g_cnt = 0ull;
__device__ float  g_sel = 0.0f;
__device__ unsigned g_done = 0u;

__device__ __forceinline__ float sig_fast(float x) {
    return __fdividef(1.0f, 1.0f + __expf(-x));
}

// One 4-cell chunk; all indices compile-time after unroll.
// Rare per-batch constants recomputed inside the excl branch from t/anchors.
__device__ __forceinline__ void process4(
    float4 vw, float4 vh, float4 vc,
    const float* pbase, int icol, int j, int kx,
    float lo, float hi, float aw, float ah,
    float gx, float gy, float gw, float gh,
    float4 t, float bw, float bh,
    float& conf2f, int& cnt, float& selv)
{
    float pw4[4] = {vw.x, vw.y, vw.z, vw.w};
    float ph4[4] = {vh.x, vh.y, vh.z, vh.w};
    float pc4[4] = {vc.x, vc.y, vc.z, vc.w};

    bool pass[4];
    bool anyp = false;
    #pragma unroll
    for (int k = 0; k < 4; k++) {
        float s = pw4[k] + ph4[k];
        pass[k] = (s > lo) && (s < hi);
        anyp |= pass[k];
    }
    bool own = (kx >= 0) && (kx < 4);
    bool noobj[4] = {true, true, true, true};

    if (anyp | own) {
        float4 vx = __ldg((const float4*)(pbase));
        float4 vy = __ldg((const float4*)(pbase + (size_t)PLANE));
        float px4[4] = {vx.x, vx.y, vx.z, vx.w};
        float py4[4] = {vy.x, vy.y, vy.z, vy.w};
        float gxm = gx - gw * 0.5f, gxM = gx + gw * 0.5f;
        float gym = gy - gh * 0.5f, gyM = gy + gh * 0.5f;
        float ga  = gw * gh;

        #pragma unroll
        for (int k = 0; k < 4; k++) {
            bool is_excl = (k == kx);
            if (pass[k] | is_excl) {
                float px = sig_fast(px4[k]) + (float)(icol + k);
                float py = sig_fast(py4[k]) + (float)j;
                float pw = __expf(pw4[k]) * aw;
                float ph = __expf(ph4[k]) * ah;
                float mx = fminf(px - pw * 0.5f, gxm);
                float Mx = fmaxf(px + pw * 0.5f, gxM);
                float my = fminf(py - ph * 0.5f, gym);
                float My = fmaxf(py + ph * 0.5f, gyM);
                float cw = pw + gw - (Mx - mx);
                float ch = ph + gh - (My - my);
                float carea = cw * ch;
                float uarea = pw * ph + ga - carea;
                noobj[k] = (cw <= 0.0f) || (ch <= 0.0f) || (carea <= THRESH * uarea);
                if (is_excl) {
                    noobj[k] = false;
                    // rare: recompute sel-loss constants locally
                    float tscale = 2.0f - t.z * t.w;
                    float xs = sig_fast(px4[k]);
                    float ys = sig_fast(py4[k]);
                    float cs = sig_fast(pc4[k]);
                    float txv = gx - floorf(gx), tyv = gy - floorf(gy);
                    float twv = __logf(__fdividef(gw, bw) + 1e-16f);
                    float thv = __logf(__fdividef(gh, bh) + 1e-16f);
                    float dx = (xs - txv) * tscale, dy = (ys - tyv) * tscale;
                    float dw = (pw4[k] - twv) * tscale, dh = (ph4[k] - thv) * tscale;
                    selv += (dx*dx + dy*dy + dw*dw + dh*dh
                          + OBJ_SCALE * (cs - 1.0f) * (cs - 1.0f)) * (1.0f / (float)NB);
                }
            }
        }
    }

    #pragma unroll
    for (int k = 0; k < 4; k++) {
        if (noobj[k]) {
            float rr = sig_fast(pc4[k]);
            conf2f += rr * rr;
            cnt++;
        }
    }
}

__global__ void __launch_bounds__(256, 6) k_fused(const float* __restrict__ out,
                                                  const float* __restrict__ tgt,
                                                  const float* __restrict__ anc,
                                                  float* __restrict__ res) {
    int tid = blockIdx.x * 256 + threadIdx.x;
    int i4 = (tid & 15) * 4;          // chunk A cols [i4, i4+4); chunk B +64
    int r  = tid >> 4;
    int j  = r & 127; r >>= 7;        // row
    int a  = r & 1;                   // anchor (block-uniform)
    int b  = r >> 1;                  // batch  (block-uniform)

    // ---- 6 front-batched streaming loads: w,h,conf for both chunks ----
    const float* pbase = out + ((size_t)(b * 10 + a * 5) * NH + j) * NW + i4;
    float4 wA = *(const float4*)(pbase + 2 * (size_t)PLANE);
    float4 wB = *(const float4*)(pbase + 2 * (size_t)PLANE + 64);
    float4 hA = *(const float4*)(pbase + 3 * (size_t)PLANE);
    float4 hB = *(const float4*)(pbase + 3 * (size_t)PLANE + 64);
    float4 cA = *(const float4*)(pbase + 4 * (size_t)PLANE);
    float4 cB = *(const float4*)(pbase + 4 * (size_t)PLANE + 64);

    // ---- per-thread constants (overlap the in-flight loads) ----
    float4 t = __ldg((const float4*)(tgt + b * 4));     // warp-broadcast
    float gx = t.x * (float)NW, gy = t.y * (float)NH;
    float gw = t.z * (float)NW, gh = t.w * (float)NH;
    float a0w = __ldg(anc + 0), a0h = __ldg(anc + 1);
    float a1w = __ldg(anc + 2), a1h = __ldg(anc + 3);

    float ga = gw * gh;
    float i0 = fminf(gw, a0w) * fminf(gh, a0h);
    float u0 = ga + 1e-16f + a0w * a0h - i0;
    float i1 = fminf(gw, a1w) * fminf(gh, a1h);
    float u1 = ga + 1e-16f + a1w * a1h - i1;
    int best = (i1 * u0 > i0 * u1) ? 1 : 0;             // u0,u1 > 0

    int excl = best * PLANE + (int)gy * NW + (int)gx;
    int kxA = excl - (a * PLANE + j * NW + i4);          // [0,3] iff chunk A owns
    int kxB = kxA - 64;                                  // [0,3] iff chunk B owns

    float aw = a ? a1w : a0w;
    float ah = a ? a1h : a0h;
    float cc = __logf(__fdividef(ga, aw * ah));
    float lo = cc - LN_MARGIN, hi = cc + LN_MARGIN;
    float bw = best ? a1w : a0w;
    float bh = best ? a1h : a0h;

    float conf2f = 0.0f;
    float selv = 0.0f;
    int cnt = 0;

    process4(wA, hA, cA, pbase,      i4,      j, kxA, lo, hi, aw, ah,
             gx, gy, gw, gh, t, bw, bh, conf2f, cnt, selv);
    process4(wB, hB, cB, pbase + 64, i4 + 64, j, kxB, lo, hi, aw, ah,
             gx, gy, gw, gh, t, bw, bh, conf2f, cnt, selv);

    // ---- block reduce (conf2, cnt, selv) ----
    #pragma unroll
    for (int o = 16; o > 0; o >>= 1) {
        conf2f += __shfl_down_sync(0xffffffffu, conf2f, o);
        cnt    += __shfl_down_sync(0xffffffffu, cnt, o);
        selv   += __shfl_down_sync(0xffffffffu, selv, o);
    }
    __shared__ double sh_c2[8];
    __shared__ int    sh_ct[8];
    __shared__ float  sh_sv[8];
    int lane = threadIdx.x & 31, wrp = threadIdx.x >> 5;
    if (lane == 0) { sh_c2[wrp] = (double)conf2f; sh_ct[wrp] = cnt; sh_sv[wrp] = selv; }
    __syncthreads();
    if (wrp == 0) {
        double c2 = (lane < 8) ? sh_c2[lane] : 0.0;
        int    ct = (lane < 8) ? sh_ct[lane] : 0;
        float  sv = (lane < 8) ? sh_sv[lane] : 0.0f;
        #pragma unroll
        for (int o = 4; o > 0; o >>= 1) {
            c2 += __shfl_down_sync(0xffffffffu, c2, o);
            ct += __shfl_down_sync(0xffffffffu, ct, o);
            sv += __shfl_down_sync(0xffffffffu, sv, o);
        }
        if (lane == 0) {
            atomicAdd(&g_conf2, c2);
            atomicAdd(&g_cnt, (unsigned long long)ct);
            if (sv != 0.0f) atomicAdd(&g_sel, sv);
            __threadfence();
            unsigned old = atomicAdd(&g_done, 1u);
            if (old == (unsigned)(NBLOCKS - 1)) {
                __threadfence();
                res[0] = g_sel + (float)(g_conf2 / (double)g_cnt);
                g_conf2 = 0.0; g_cnt = 0ull; g_sel = 0.0f; g_done = 0u;
            }
        }
    }
}

extern "C" void kernel_launch(void* const* d_in, const int* in_sizes, int n_in,
                              void* d_out, int out_size) {
    const float* out = (const float*)d_in[0];   // (128, 10, 128, 128)
    const float* tgt = (const float*)d_in[1];   // (128, 4)
    const float* anc = (const float*)d_in[2];   // (2, 2)
    float* res = (float*)d_out;

    k_fused<<<NBLOCKS, 256>>>(out, tgt, anc, res);
}